// round 4
// baseline (speedup 1.0000x reference)
#include <cuda_runtime.h>
#include <cuda_bf16.h>
#include <math.h>

#define NI 32
#define NH 1024
#define NO 64
#define MB 8
#define THREADS 1024
#define KPAD 36   // padded k-dimension (33 -> 36 floats, 16B aligned rows)

// Scratch (no device allocation allowed): packed per-step weights.
// W2P[i][j][k]: weight W2[g(j)][h(k)] for step i, zero-padded.
// W3P[i][o][k]: masked W3[o][g=i+31k], zero when (o&31) <= i or k >= cnt.
// W1P[i][j]   : W1[h(j)][i] for step-i target enumeration j.
__device__ float g_W2P[31 * 1024 * KPAD];   // 4.5 MB
__device__ float g_W3P[31 * NO * KPAD];     // 285 KB
__device__ float g_W1P[31 * 1024];          // 127 KB

// ---------------- prep kernel (single launch) ----------------

__global__ void prep_all(const float* __restrict__ W1,
                         const float* __restrict__ W2,
                         const float* __restrict__ W3) {
    int idx = blockIdx.x * blockDim.x + threadIdx.x;

    // W2P: 31 * 1024 * 36 = 1,142,784 elements
    if (idx < 31 * 1024 * KPAD) {
        int i   = idx / (1024 * KPAD);
        int rem = idx - i * (1024 * KPAD);
        int j   = rem / KPAD;
        int k   = rem - j * KPAD;
        int w   = 31 - i;
        int cnt = (i == 0) ? 34 : 33;
        int nv  = 33 * w + ((i == 0) ? 1 : 0);
        float val = 0.f;
        if (j < nv && k < cnt) {
            int q = j / w;
            int r = i + (j - q * w);
            int g = 31 * q + r;
            int h = i + 31 * k;
            val = W2[g * NH + h];
        }
        g_W2P[idx] = val;
    }

    // W3P: 31 * 64 * 36 = 71,424 elements
    if (idx < 31 * NO * KPAD) {
        int i   = idx / (NO * KPAD);
        int rem = idx - i * (NO * KPAD);
        int o   = rem / KPAD;
        int k   = rem - o * KPAD;
        int cnt = (i == 0) ? 34 : 33;
        float val = 0.f;
        if (k < cnt && (o & 31) > i) {
            int g = i + 31 * k;
            val = W3[o * NH + g];
        }
        g_W3P[idx] = val;
    }

    // W1P: 31 * 1024 elements
    if (idx < 31 * 1024) {
        int i = idx >> 10;
        int j = idx & 1023;
        int w = 31 - i;
        int nv = 33 * w + ((i == 0) ? 1 : 0);
        float val = 0.f;
        if (j < nv) {
            int q = j / w;
            int r = i + (j - q * w);
            int h = 31 * q + r;
            val = W1[h * NI + i];
        }
        g_W1P[idx] = val;
    }
}

// ---------------- main kernel ----------------
//
// Per CTA: MB batch rows. Running pre-activations z1[MB][NH], z2[MB][NH],
// z3[MB][64] in smem. 32 sequential steps; at step i the ~33 hidden units
// with degree == i (deg(h) = h % 31) become final and are pushed forward as
// rank-33 updates. Targets at step i: (h % 31) >= i, enumerated j ->
// (q = j/w, r = i + j%w, h = 31q + r), w = 31 - i. Max nv = 1024 == THREADS.

__global__ void __launch_bounds__(THREADS)
made_kernel(const float* __restrict__ inp,
            const float* __restrict__ b1,
            const float* __restrict__ b2,
            const float* __restrict__ b3,
            float* __restrict__ out, int B) {
    extern __shared__ float smem[];
    float* z1s = smem;                    // MB*NH
    float* z2s = z1s + MB * NH;           // MB*NH
    float* z3s = z2s + MB * NH;           // MB*NO
    float* xs  = z3s + MB * NO;           // MB*NI  (produced x, for output)
    float* xin = xs  + MB * NI;           // MB*NI  (staged inputs)
    float* h1g = xin + MB * NI;           // KPAD*MB
    float* h2g = h1g + KPAD * MB;         // KPAD*MB
    float* Js  = h2g + KPAD * MB;         // MB

    const int tid  = threadIdx.x;
    const int lane = tid & 31;
    const int b0   = blockIdx.x * MB;

    // init state
    for (int idx = tid; idx < MB * NH; idx += THREADS) {
        int h = idx & (NH - 1);
        z1s[idx] = b1[h];
        z2s[idx] = b2[h];
    }
    if (tid < MB * NO) z3s[tid] = b3[tid & (NO - 1)];
    if (tid < MB * NI) {
        int mb = tid >> 5, ii = tid & 31;
        xin[tid] = inp[(b0 + mb) * NI + ii];
    }
    if (tid < 2 * KPAD * MB) h1g[tid] = 0.f;   // zero h1g+h2g tails
    if (tid < MB) Js[tid] = 0.f;
    __syncthreads();

    for (int i = 0; i < NI; ++i) {
        // ---- Phase A (fused, per-warp): produce x_i, broadcast via shuffle ----
        float xv[MB];
        {
            float x = 0.f, a = 0.f;
            if (lane < MB) {
                float m = z3s[lane * NO + i];
                a = tanhf(z3s[lane * NO + 32 + i]);
                x = xin[lane * NI + i] * expf(a) + m;
            }
            #pragma unroll
            for (int mb = 0; mb < MB; ++mb)
                xv[mb] = __shfl_sync(0xffffffffu, x, mb);
            if (tid < MB) {            // warp 0 records outputs
                xs[tid * NI + i] = x;
                Js[tid] -= a;
            }
        }
        if (i == NI - 1) break;

        const int w  = 31 - i;
        const int nv = 33 * w + ((i == 0) ? 1 : 0);

        int q = 0, r = 0, hg = 0;
        const bool act = (tid < nv);
        if (act) {
            q  = tid / w;
            r  = i + (tid - q * w);
            hg = 31 * q + r;
        }
        const bool grp = act && (r == i);

        // ---- Phase B: rank-1 z1 update + extract newly-final h1 group ----
        if (act) {
            const float w1 = g_W1P[i * 1024 + tid];
            float zz[MB];
            #pragma unroll
            for (int mb = 0; mb < MB; ++mb) {
                float z = z1s[mb * NH + hg] + w1 * xv[mb];
                z1s[mb * NH + hg] = z;
                zz[mb] = z;
            }
            if (grp) {
                #pragma unroll
                for (int mb = 0; mb < MB; ++mb)
                    h1g[q * MB + mb] = fmaxf(zz[mb], 0.f);
            }
        }
        __syncthreads();

        // ---- Phase C: rank-33 z2 update + extract h2 group ----
        if (act) {
            float acc[MB];
            #pragma unroll
            for (int mb = 0; mb < MB; ++mb) acc[mb] = 0.f;
            const float4* wrow =
                (const float4*)&g_W2P[((long)i * 1024 + tid) * KPAD];
            #pragma unroll
            for (int k4 = 0; k4 < KPAD / 4; ++k4) {
                float4 wv = __ldg(wrow + k4);
                #pragma unroll
                for (int kk = 0; kk < 4; ++kk) {
                    int k = 4 * k4 + kk;
                    float wgt = (kk == 0) ? wv.x : (kk == 1) ? wv.y
                              : (kk == 2) ? wv.z : wv.w;
                    float4 hv0 = *(const float4*)&h1g[k * MB];
                    float4 hv1 = *(const float4*)&h1g[k * MB + 4];
                    acc[0] += wgt * hv0.x; acc[1] += wgt * hv0.y;
                    acc[2] += wgt * hv0.z; acc[3] += wgt * hv0.w;
                    acc[4] += wgt * hv1.x; acc[5] += wgt * hv1.y;
                    acc[6] += wgt * hv1.z; acc[7] += wgt * hv1.w;
                }
            }
            float zz[MB];
            #pragma unroll
            for (int mb = 0; mb < MB; ++mb) {
                float z = z2s[mb * NH + hg] + acc[mb];
                z2s[mb * NH + hg] = z;
                zz[mb] = z;
            }
            if (grp) {
                #pragma unroll
                for (int mb = 0; mb < MB; ++mb)
                    h2g[q * MB + mb] = fmaxf(zz[mb], 0.f);
            }
        }
        __syncthreads();

        // ---- Phase D: z3 update (mask baked into W3P zeros) ----
        if (tid < MB * NO) {
            const int mb = tid >> 6;
            const int o  = tid & (NO - 1);
            const float4* wrow = (const float4*)&g_W3P[(i * NO + o) * KPAD];
            float acc = 0.f;
            #pragma unroll
            for (int k4 = 0; k4 < KPAD / 4; ++k4) {
                float4 wv = __ldg(wrow + k4);
                int k = 4 * k4;
                acc += wv.x * h2g[(k + 0) * MB + mb];
                acc += wv.y * h2g[(k + 1) * MB + mb];
                acc += wv.z * h2g[(k + 2) * MB + mb];
                acc += wv.w * h2g[(k + 3) * MB + mb];
            }
            z3s[tid] += acc;
        }
        __syncthreads();
    }

    // ---- outputs: x (B x NI) then J (B) ----
    if (tid < MB * NI) {
        int mb = tid >> 5;
        int ii = tid & (NI - 1);
        out[(b0 + mb) * NI + ii] = xs[mb * NI + ii];
    }
    if (tid < MB) out[B * NI + b0 + tid] = Js[tid];
}

// ---------------- launcher ----------------

extern "C" void kernel_launch(void* const* d_in, const int* in_sizes, int n_in,
                              void* d_out, int out_size) {
    const float* inputs = (const float*)d_in[0];
    const float* W1     = (const float*)d_in[1];
    const float* b1     = (const float*)d_in[2];
    const float* W2     = (const float*)d_in[3];
    const float* b2     = (const float*)d_in[4];
    const float* W3     = (const float*)d_in[5];
    const float* b3     = (const float*)d_in[6];

    int B = in_sizes[0] / NI;

    size_t smem_bytes = (size_t)(MB * NH * 2 + MB * NO + MB * NI * 2
                                 + KPAD * MB * 2 + MB) * sizeof(float);
    static bool attr_set = false;
    if (!attr_set) {
        cudaFuncSetAttribute(made_kernel,
                             cudaFuncAttributeMaxDynamicSharedMemorySize,
                             (int)smem_bytes);
        attr_set = true;
    }

    int prep_elems = 31 * 1024 * KPAD;
    prep_all<<<(prep_elems + 1023) / 1024, 1024>>>(W1, W2, W3);
    made_kernel<<<B / MB, THREADS, smem_bytes>>>(inputs, b1, b2, b3,
                                                 (float*)d_out, B);
}

// round 5
// speedup vs baseline: 1.3188x; 1.3188x over previous
#include <cuda_runtime.h>
#include <cuda_bf16.h>
#include <math.h>

#define NI 32
#define NH 1024
#define NO 64
#define MB 8
#define THREADS 1024
#define KPAD 36
#define K4 (KPAD / 4)   // 9

// Packed per-step weights, WARP-COALESCED layouts (fast dim = thread id):
// g_W2P4[((i*K4 + k4)*1024 + j)] : float4 of W2[g(j)][h(i+31*(4k4+kk))], kk=0..3
// g_W3P4[((i*K4 + k4)*64 + o)]   : float4 of masked W3[o][i+31*(4k4+kk)]
// g_W1P [i*1024 + j]             : W1[h(j)][i]
__device__ float4 g_W2P4[31 * K4 * 1024];   // 4.5 MB
__device__ float4 g_W3P4[31 * K4 * NO];     // 285 KB
__device__ float  g_W1P [31 * 1024];        // 127 KB

// ---------------- prep kernel ----------------

__global__ void prep_all(const float* __restrict__ W1,
                         const float* __restrict__ W2,
                         const float* __restrict__ W3) {
    int idx = blockIdx.x * blockDim.x + threadIdx.x;

    // W2P4: 31 * 9 * 1024 float4s
    if (idx < 31 * K4 * 1024) {
        int i   = idx / (K4 * 1024);
        int rem = idx - i * (K4 * 1024);
        int k4  = rem >> 10;
        int j   = rem & 1023;
        int w   = 31 - i;
        int cnt = (i == 0) ? 34 : 33;
        int nv  = 33 * w + ((i == 0) ? 1 : 0);
        float4 v = make_float4(0.f, 0.f, 0.f, 0.f);
        if (j < nv) {
            int q = j / w;
            int r = i + (j - q * w);
            int g = 31 * q + r;
            float* vp = &v.x;
            #pragma unroll
            for (int kk = 0; kk < 4; ++kk) {
                int k = 4 * k4 + kk;
                if (k < cnt) vp[kk] = W2[g * NH + (i + 31 * k)];
            }
        }
        g_W2P4[idx] = v;
    }

    // W3P4: 31 * 9 * 64 float4s
    if (idx < 31 * K4 * NO) {
        int i   = idx / (K4 * NO);
        int rem = idx - i * (K4 * NO);
        int k4  = rem >> 6;
        int o   = rem & (NO - 1);
        int cnt = (i == 0) ? 34 : 33;
        float4 v = make_float4(0.f, 0.f, 0.f, 0.f);
        if ((o & 31) > i) {
            float* vp = &v.x;
            #pragma unroll
            for (int kk = 0; kk < 4; ++kk) {
                int k = 4 * k4 + kk;
                if (k < cnt) vp[kk] = W3[o * NH + (i + 31 * k)];
            }
        }
        g_W3P4[idx] = v;
    }

    // W1P: 31 * 1024
    if (idx < 31 * 1024) {
        int i = idx >> 10;
        int j = idx & 1023;
        int w = 31 - i;
        int nv = 33 * w + ((i == 0) ? 1 : 0);
        float val = 0.f;
        if (j < nv) {
            int q = j / w;
            int r = i + (j - q * w);
            val = W1[(31 * q + r) * NI + i];
        }
        g_W1P[idx] = val;
    }
}

// ---------------- main kernel ----------------

__global__ void __launch_bounds__(THREADS)
made_kernel(const float* __restrict__ inp,
            const float* __restrict__ b1,
            const float* __restrict__ b2,
            const float* __restrict__ b3,
            float* __restrict__ out, int B) {
    extern __shared__ float smem[];
    float* z1s  = smem;                     // MB*NH
    float* z2s  = z1s + MB * NH;            // MB*NH
    float* z3s  = z2s + MB * NH;            // MB*NO
    float* xs   = z3s + MB * NO;            // MB*NI
    float* xin  = xs  + MB * NI;            // MB*NI
    float* h1g  = xin + MB * NI;            // KPAD*MB   ([k][mb])
    float* h2g  = h1g + KPAD * MB;          // KPAD*MB   ([k][mb])
    float* h2gT = h2g + KPAD * MB;          // MB*KPAD   ([mb][k], for Phase D)
    float* Js   = h2gT + MB * KPAD;         // MB

    const int tid  = threadIdx.x;
    const int lane = tid & 31;
    const int b0   = blockIdx.x * MB;

    // init state
    for (int idx = tid; idx < MB * NH; idx += THREADS) {
        int h = idx & (NH - 1);
        z1s[idx] = b1[h];
        z2s[idx] = b2[h];
    }
    if (tid < MB * NO) z3s[tid] = b3[tid & (NO - 1)];
    if (tid < MB * NI) {
        int mb = tid >> 5, ii = tid & 31;
        xin[tid] = inp[(b0 + mb) * NI + ii];
    }
    if (tid < 2 * KPAD * MB) h1g[tid] = 0.f;   // zero h1g + h2g
    if (tid < MB * KPAD) h2gT[tid] = 0.f;
    if (tid < MB) Js[tid] = 0.f;
    __syncthreads();

    for (int i = 0; i < NI; ++i) {
        // ---- Phase A (per-warp, fused): produce x_i, broadcast via shuffle ----
        float xv[MB];
        {
            float x = 0.f, a = 0.f;
            if (lane < MB) {
                float m = z3s[lane * NO + i];
                a = tanhf(z3s[lane * NO + 32 + i]);
                x = xin[lane * NI + i] * expf(a) + m;
            }
            #pragma unroll
            for (int mb = 0; mb < MB; ++mb)
                xv[mb] = __shfl_sync(0xffffffffu, x, mb);
            if (tid < MB) {
                xs[tid * NI + i] = x;
                Js[tid] -= a;
            }
        }
        if (i == NI - 1) break;

        const int w  = 31 - i;
        const int nv = 33 * w + ((i == 0) ? 1 : 0);

        int q = 0, r = 0, hg = 0;
        const bool act = (tid < nv);
        if (act) {
            q  = tid / w;
            r  = i + (tid - q * w);
            hg = 31 * q + r;
        }
        const bool grp = act && (r == i);

        // ---- Phase B: rank-1 z1 update + extract newly-final h1 group ----
        if (act) {
            const float w1 = g_W1P[i * 1024 + tid];
            float zz[MB];
            #pragma unroll
            for (int mb = 0; mb < MB; ++mb) {
                float z = z1s[mb * NH + hg] + w1 * xv[mb];
                z1s[mb * NH + hg] = z;
                zz[mb] = z;
            }
            if (grp) {
                #pragma unroll
                for (int mb = 0; mb < MB; ++mb)
                    h1g[q * MB + mb] = fmaxf(zz[mb], 0.f);
            }
        }
        __syncthreads();

        // ---- Phase C: rank-33 z2 update + extract h2 group ----
        if (act) {
            float acc[MB];
            #pragma unroll
            for (int mb = 0; mb < MB; ++mb) acc[mb] = 0.f;
            const float4* wbase = g_W2P4 + (long)i * K4 * 1024 + tid;
            #pragma unroll
            for (int k4 = 0; k4 < K4; ++k4) {
                float4 wv = __ldg(wbase + k4 * 1024);   // coalesced across warp
                const float* wp = &wv.x;
                #pragma unroll
                for (int kk = 0; kk < 4; ++kk) {
                    int k = 4 * k4 + kk;
                    float wgt = wp[kk];
                    float4 hv0 = *(const float4*)&h1g[k * MB];
                    float4 hv1 = *(const float4*)&h1g[k * MB + 4];
                    acc[0] += wgt * hv0.x; acc[1] += wgt * hv0.y;
                    acc[2] += wgt * hv0.z; acc[3] += wgt * hv0.w;
                    acc[4] += wgt * hv1.x; acc[5] += wgt * hv1.y;
                    acc[6] += wgt * hv1.z; acc[7] += wgt * hv1.w;
                }
            }
            float zz[MB];
            #pragma unroll
            for (int mb = 0; mb < MB; ++mb) {
                float z = z2s[mb * NH + hg] + acc[mb];
                z2s[mb * NH + hg] = z;
                zz[mb] = z;
            }
            if (grp) {
                #pragma unroll
                for (int mb = 0; mb < MB; ++mb) {
                    float hval = fmaxf(zz[mb], 0.f);
                    h2g[q * MB + mb]   = hval;   // (kept for symmetry)
                    h2gT[mb * KPAD + q] = hval;  // Phase D layout
                }
            }
        }
        __syncthreads();

        // ---- Phase D: z3 update (mask baked into W3P4 zeros) ----
        if (tid < MB * NO) {
            const int mb = tid >> 6;
            const int o  = tid & (NO - 1);
            const float4* wb = g_W3P4 + (long)i * K4 * NO + o;
            const float4* hb = (const float4*)&h2gT[mb * KPAD];
            float acc = 0.f;
            #pragma unroll
            for (int k4 = 0; k4 < K4; ++k4) {
                float4 wv = __ldg(wb + k4 * NO);   // coalesced across o
                float4 hv = hb[k4];                // uniform LDS.128
                acc += wv.x * hv.x + wv.y * hv.y + wv.z * hv.z + wv.w * hv.w;
            }
            z3s[tid] += acc;
        }
        __syncthreads();
    }

    // ---- outputs: x (B x NI) then J (B) ----
    if (tid < MB * NI) {
        int mb = tid >> 5;
        int ii = tid & (NI - 1);
        out[(b0 + mb) * NI + ii] = xs[mb * NI + ii];
    }
    if (tid < MB) out[B * NI + b0 + tid] = Js[tid];
}

// ---------------- launcher ----------------

extern "C" void kernel_launch(void* const* d_in, const int* in_sizes, int n_in,
                              void* d_out, int out_size) {
    const float* inputs = (const float*)d_in[0];
    const float* W1     = (const float*)d_in[1];
    const float* b1     = (const float*)d_in[2];
    const float* W2     = (const float*)d_in[3];
    const float* b2     = (const float*)d_in[4];
    const float* W3     = (const float*)d_in[5];
    const float* b3     = (const float*)d_in[6];

    int B = in_sizes[0] / NI;

    size_t smem_bytes = (size_t)(MB * NH * 2 + MB * NO + MB * NI * 2
                                 + KPAD * MB * 3 + MB) * sizeof(float);
    static bool attr_set = false;
    if (!attr_set) {
        cudaFuncSetAttribute(made_kernel,
                             cudaFuncAttributeMaxDynamicSharedMemorySize,
                             (int)smem_bytes);
        attr_set = true;
    }

    int prep_elems = 31 * K4 * 1024;   // largest pack
    prep_all<<<(prep_elems + 1023) / 1024, 1024>>>(W1, W2, W3);
    made_kernel<<<B / MB, THREADS, smem_bytes>>>(inputs, b1, b2, b3,
                                                 (float*)d_out, B);
}

// round 6
// speedup vs baseline: 1.4160x; 1.0738x over previous
#include <cuda_runtime.h>
#include <cuda_bf16.h>
#include <math.h>

#define NI 32
#define NH 1024
#define NO 64
#define MB 8
#define THREADS 512
#define KPAD 36
#define K4 (KPAD / 4)   // 9

// Packed per-step weights, warp-coalesced (fast dim = target index):
// g_W2P4[(i*K4 + k4)*1024 + j] : float4 of W2[g(j)][h(i+31*(4k4+kk))], zero for j>=nv or k>=cnt
// g_W3P4[(i*K4 + k4)*64 + o]   : float4 of masked W3[o][i+31*k]
// g_W1P [i*1024 + j]           : W1[h(j)][i], zero for j>=nv
__device__ float4 g_W2P4[31 * K4 * 1024];   // 4.5 MB
__device__ float4 g_W3P4[31 * K4 * NO];     // 285 KB
__device__ float  g_W1P [31 * 1024];        // 127 KB

// ---- packed f32x2 helpers (Blackwell FFMA2) ----
__device__ __forceinline__ unsigned long long pack2(float v) {
    unsigned long long d; unsigned int u = __float_as_uint(v);
    asm("mov.b64 %0, {%1, %1};" : "=l"(d) : "r"(u));
    return d;
}
__device__ __forceinline__ unsigned long long fma2(unsigned long long a,
                                                   unsigned long long b,
                                                   unsigned long long c) {
    unsigned long long d;
    asm("fma.rn.f32x2 %0, %1, %2, %3;" : "=l"(d) : "l"(a), "l"(b), "l"(c));
    return d;
}
__device__ __forceinline__ float2 unpack2(unsigned long long v) {
    unsigned int lo, hi;
    asm("mov.b64 {%0, %1}, %2;" : "=r"(lo), "=r"(hi) : "l"(v));
    return make_float2(__uint_as_float(lo), __uint_as_float(hi));
}

// ---------------- prep kernel ----------------

__global__ void prep_all(const float* __restrict__ W1,
                         const float* __restrict__ W2,
                         const float* __restrict__ W3) {
    int idx = blockIdx.x * blockDim.x + threadIdx.x;

    if (idx < 31 * K4 * 1024) {
        int i   = idx / (K4 * 1024);
        int rem = idx - i * (K4 * 1024);
        int k4  = rem >> 10;
        int j   = rem & 1023;
        int w   = 31 - i;
        int cnt = (i == 0) ? 34 : 33;
        int nv  = 33 * w + ((i == 0) ? 1 : 0);
        float4 v = make_float4(0.f, 0.f, 0.f, 0.f);
        if (j < nv) {
            int q = j / w;
            int r = i + (j - q * w);
            int g = 31 * q + r;
            float* vp = &v.x;
            #pragma unroll
            for (int kk = 0; kk < 4; ++kk) {
                int k = 4 * k4 + kk;
                if (k < cnt) vp[kk] = W2[g * NH + (i + 31 * k)];
            }
        }
        g_W2P4[idx] = v;
    }

    if (idx < 31 * K4 * NO) {
        int i   = idx / (K4 * NO);
        int rem = idx - i * (K4 * NO);
        int k4  = rem >> 6;
        int o   = rem & (NO - 1);
        int cnt = (i == 0) ? 34 : 33;
        float4 v = make_float4(0.f, 0.f, 0.f, 0.f);
        if ((o & 31) > i) {
            float* vp = &v.x;
            #pragma unroll
            for (int kk = 0; kk < 4; ++kk) {
                int k = 4 * k4 + kk;
                if (k < cnt) vp[kk] = W3[o * NH + (i + 31 * k)];
            }
        }
        g_W3P4[idx] = v;
    }

    if (idx < 31 * 1024) {
        int i = idx >> 10;
        int j = idx & 1023;
        int w = 31 - i;
        int nv = 33 * w + ((i == 0) ? 1 : 0);
        float val = 0.f;
        if (j < nv) {
            int q = j / w;
            int r = i + (j - q * w);
            val = W1[(31 * q + r) * NI + i];
        }
        g_W1P[idx] = val;
    }
}

// ---------------- main kernel ----------------

__global__ void __launch_bounds__(THREADS)
made_kernel(const float* __restrict__ inp,
            const float* __restrict__ b1,
            const float* __restrict__ b2,
            const float* __restrict__ b3,
            float* __restrict__ out, int B) {
    extern __shared__ float smem[];
    float* z1s  = smem;                     // MB*NH  ([mb][h])
    float* z2s  = z1s + MB * NH;            // MB*NH  ([mb][h])
    float* z3s  = z2s + MB * NH;            // MB*NO
    float* xs   = z3s + MB * NO;            // MB*NI
    float* xin  = xs  + MB * NI;            // MB*NI
    float* h1g  = xin + MB * NI;            // KPAD*MB ([k][mb], 16B aligned rows)
    float* h2gT = h1g + KPAD * MB;          // MB*KPAD ([mb][k])
    float* Js   = h2gT + MB * KPAD;         // MB

    const int tid  = threadIdx.x;
    const int lane = tid & 31;
    const int b0   = blockIdx.x * MB;

    // init state
    for (int idx = tid; idx < MB * NH; idx += THREADS) {
        int h = idx & (NH - 1);
        z1s[idx] = b1[h];
        z2s[idx] = b2[h];
    }
    if (tid < MB * NO) z3s[tid] = b3[tid & (NO - 1)];
    if (tid < MB * NI) {
        int mb = tid >> 5, ii = tid & 31;
        xin[tid] = inp[(b0 + mb) * NI + ii];
    }
    if (tid < KPAD * MB) h1g[tid] = 0.f;
    if (tid < MB * KPAD) h2gT[tid] = 0.f;
    if (tid < MB) Js[tid] = 0.f;
    __syncthreads();

    for (int i = 0; i < NI; ++i) {
        // ---- Phase A (per-warp, fused): produce x_i, broadcast via shuffle ----
        float xv[MB];
        {
            float x = 0.f, a = 0.f;
            if (lane < MB) {
                float m = z3s[lane * NO + i];
                a = tanhf(z3s[lane * NO + 32 + i]);
                x = xin[lane * NI + i] * expf(a) + m;
            }
            #pragma unroll
            for (int mb = 0; mb < MB; ++mb)
                xv[mb] = __shfl_sync(0xffffffffu, x, mb);
            if (tid < MB) {
                xs[tid * NI + i] = x;
                Js[tid] -= a;
            }
        }
        if (i == NI - 1) break;

        const int w  = 31 - i;
        const int nv = 33 * w + ((i == 0) ? 1 : 0);
        const int j0 = tid;
        const int j1 = tid + 512;
        const bool act0 = (j0 < nv);
        const bool act1 = (j1 < nv);

        int q0 = 0, r0 = 0, hg0 = 0, q1 = 0, r1 = 0, hg1 = 0;
        if (act0) { q0 = j0 / w; r0 = i + (j0 - q0 * w); hg0 = 31 * q0 + r0; }
        if (act1) { q1 = j1 / w; r1 = i + (j1 - q1 * w); hg1 = 31 * q1 + r1; }

        // ---- Phase B: rank-1 z1 update + extract newly-final h1 group ----
        if (act0) {
            const float w1 = g_W1P[i * 1024 + j0];
            #pragma unroll
            for (int mb = 0; mb < MB; ++mb) {
                float z = z1s[mb * NH + hg0] + w1 * xv[mb];
                z1s[mb * NH + hg0] = z;
                if (r0 == i) h1g[q0 * MB + mb] = fmaxf(z, 0.f);
            }
        }
        if (act1) {
            const float w1 = g_W1P[i * 1024 + j1];
            #pragma unroll
            for (int mb = 0; mb < MB; ++mb) {
                float z = z1s[mb * NH + hg1] + w1 * xv[mb];
                z1s[mb * NH + hg1] = z;
                if (r1 == i) h1g[q1 * MB + mb] = fmaxf(z, 0.f);
            }
        }
        __syncthreads();

        // ---- Phase C: rank-33 z2 update (2 targets/thread, f32x2 FMA) ----
        if (act0) {   // act1 implies act0; warps fully past nv skip
            unsigned long long acc0[4] = {0ull, 0ull, 0ull, 0ull};
            unsigned long long acc1[4] = {0ull, 0ull, 0ull, 0ull};
            const float4* wb = g_W2P4 + (long)i * K4 * 1024;
            const ulonglong2* hb = (const ulonglong2*)h1g;
            #pragma unroll
            for (int k4 = 0; k4 < K4; ++k4) {
                float4 w0 = __ldg(wb + k4 * 1024 + j0);   // zero-padded if j>=nv
                float4 w1 = __ldg(wb + k4 * 1024 + j1);
                const float* wp0 = &w0.x;
                const float* wp1 = &w1.x;
                #pragma unroll
                for (int kk = 0; kk < 4; ++kk) {
                    int k = 4 * k4 + kk;
                    ulonglong2 hA = hb[2 * k];       // mb 0..3
                    ulonglong2 hB = hb[2 * k + 1];   // mb 4..7
                    unsigned long long wq0 = pack2(wp0[kk]);
                    unsigned long long wq1 = pack2(wp1[kk]);
                    acc0[0] = fma2(wq0, hA.x, acc0[0]);
                    acc0[1] = fma2(wq0, hA.y, acc0[1]);
                    acc0[2] = fma2(wq0, hB.x, acc0[2]);
                    acc0[3] = fma2(wq0, hB.y, acc0[3]);
                    acc1[0] = fma2(wq1, hA.x, acc1[0]);
                    acc1[1] = fma2(wq1, hA.y, acc1[1]);
                    acc1[2] = fma2(wq1, hB.x, acc1[2]);
                    acc1[3] = fma2(wq1, hB.y, acc1[3]);
                }
            }
            {
                float a[MB];
                #pragma unroll
                for (int p = 0; p < 4; ++p) {
                    float2 f = unpack2(acc0[p]);
                    a[2 * p] = f.x; a[2 * p + 1] = f.y;
                }
                #pragma unroll
                for (int mb = 0; mb < MB; ++mb) {
                    float z = z2s[mb * NH + hg0] + a[mb];
                    z2s[mb * NH + hg0] = z;
                    if (r0 == i) h2gT[mb * KPAD + q0] = fmaxf(z, 0.f);
                }
            }
            if (act1) {
                float a[MB];
                #pragma unroll
                for (int p = 0; p < 4; ++p) {
                    float2 f = unpack2(acc1[p]);
                    a[2 * p] = f.x; a[2 * p + 1] = f.y;
                }
                #pragma unroll
                for (int mb = 0; mb < MB; ++mb) {
                    float z = z2s[mb * NH + hg1] + a[mb];
                    z2s[mb * NH + hg1] = z;
                    if (r1 == i) h2gT[mb * KPAD + q1] = fmaxf(z, 0.f);
                }
            }
        }
        __syncthreads();

        // ---- Phase D: z3 update (mask baked into W3P4 zeros), exact fit ----
        {
            const int mb = tid >> 6;
            const int o  = tid & (NO - 1);
            const float4* wb = g_W3P4 + (long)i * K4 * NO + o;
            const float4* hv = (const float4*)&h2gT[mb * KPAD];
            float acc = 0.f;
            #pragma unroll
            for (int k4 = 0; k4 < K4; ++k4) {
                float4 wv = __ldg(wb + k4 * NO);   // coalesced across o
                float4 hq = hv[k4];                // broadcast LDS.128
                acc += wv.x * hq.x + wv.y * hq.y + wv.z * hq.z + wv.w * hq.w;
            }
            z3s[tid] += acc;
        }
        __syncthreads();
    }

    // ---- outputs: x (B x NI) then J (B) ----
    if (tid < MB * NI) {
        int mb = tid >> 5;
        int ii = tid & (NI - 1);
        out[(b0 + mb) * NI + ii] = xs[mb * NI + ii];
    }
    if (tid < MB) out[B * NI + b0 + tid] = Js[tid];
}

// ---------------- launcher ----------------

extern "C" void kernel_launch(void* const* d_in, const int* in_sizes, int n_in,
                              void* d_out, int out_size) {
    const float* inputs = (const float*)d_in[0];
    const float* W1     = (const float*)d_in[1];
    const float* b1     = (const float*)d_in[2];
    const float* W2     = (const float*)d_in[3];
    const float* b2     = (const float*)d_in[4];
    const float* W3     = (const float*)d_in[5];
    const float* b3     = (const float*)d_in[6];

    int B = in_sizes[0] / NI;

    size_t smem_bytes = (size_t)(MB * NH * 2 + MB * NO + MB * NI * 2
                                 + KPAD * MB * 2 + MB) * sizeof(float);
    static bool attr_set = false;
    if (!attr_set) {
        cudaFuncSetAttribute(made_kernel,
                             cudaFuncAttributeMaxDynamicSharedMemorySize,
                             (int)smem_bytes);
        attr_set = true;
    }

    int prep_elems = 31 * K4 * 1024;
    prep_all<<<(prep_elems + 1023) / 1024, 1024>>>(W1, W2, W3);
    made_kernel<<<B / MB, THREADS, smem_bytes>>>(inputs, b1, b2, b3,
                                                 (float*)d_out, B);
}